// round 14
// baseline (speedup 1.0000x reference)
#include <cuda_runtime.h>
#include <cuda_fp16.h>
#include <cstdint>

#define NN   50000
#define EE   800000
#define ETOT 850000            // EE + NN self loops
#define FIN  128
#define HH   4
#define HID  32
#define F1   128               // HH*HID
#define CLS  40
#define W2C  48                // padded W2 cols
#define NEG  0.2f

// ---------------- scratch -----------------------------------------------------
__device__ __half2 g_h1h[(size_t)NN * 64];   // h1 in fp16, 64 half2 per row
__device__ __half  g_W1h[FIN * F1];          // W1 in fp16, [k][c]
__device__ __half  g_W2h[FIN * W2C];         // W2 in fp16, [k][c], cols 40..47 = 0
__device__ float  g_as1[NN * HH];
__device__ float  g_ad1[NN * HH];
__device__ float  g_out1[(size_t)NN * F1];
__device__ __half g_h2h[(size_t)NN * CLS];   // h2 in fp16
__device__ float  g_as2[NN];
__device__ float  g_ad2[NN];
__device__ int    g_deg[NN];                 // zero at entry of every call (BSS / re-zeroed by k_scan)
__device__ int    g_rowptr[NN + 1];
__device__ int    g_cursor[NN];
__device__ int    g_csrc[ETOT];              // src ids sorted by dst

// ---------------- helpers ------------------------------------------------------
__device__ __forceinline__ float lrelu(float v) { return v > 0.f ? v : NEG * v; }

__device__ __forceinline__ __half2 u2h(unsigned u) {
    return *reinterpret_cast<__half2*>(&u);
}
__device__ __forceinline__ unsigned pack2(float a, float b) {
    __half2 h = __floats2half2_rn(a, b);
    return *reinterpret_cast<unsigned*>(&h);
}

__device__ __forceinline__ int detect64(const void* ei) {
    const int* p = (const int*)ei;
    int is64 = 1;
    #pragma unroll
    for (int j = 0; j < 8; j++)
        if (p[2 * j + 1] != 0) is64 = 0;
    return is64;
}

__device__ __forceinline__ void decode_edge(const void* ei, int is64, int e,
                                            int& s, int& d) {
    if (e < EE) {
        if (is64) {
            const long long* p = (const long long*)ei;
            s = (int)p[e];
            d = (int)p[EE + e];
        } else {
            const int* p = (const int*)ei;
            s = p[e];
            d = p[EE + e];
        }
    } else {
        s = d = e - EE;  // self loop
    }
}

__device__ __forceinline__ void ldsm4(uint32_t* r, const void* p) {
    unsigned a = (unsigned)__cvta_generic_to_shared(p);
    asm volatile("ldmatrix.sync.aligned.m8n8.x4.shared.b16 {%0,%1,%2,%3}, [%4];"
        : "=r"(r[0]), "=r"(r[1]), "=r"(r[2]), "=r"(r[3]) : "r"(a));
}
__device__ __forceinline__ void ldsm4t(uint32_t* r, const void* p) {
    unsigned a = (unsigned)__cvta_generic_to_shared(p);
    asm volatile("ldmatrix.sync.aligned.m8n8.x4.trans.shared.b16 {%0,%1,%2,%3}, [%4];"
        : "=r"(r[0]), "=r"(r[1]), "=r"(r[2]), "=r"(r[3]) : "r"(a));
}
__device__ __forceinline__ void mma16816(float* c, const uint32_t* a,
                                         const uint32_t* b) {
    asm volatile("mma.sync.aligned.m16n8k16.row.col.f32.f16.f16.f32 "
        "{%0,%1,%2,%3}, {%4,%5,%6,%7}, {%8,%9}, {%0,%1,%2,%3};"
        : "+f"(c[0]), "+f"(c[1]), "+f"(c[2]), "+f"(c[3])
        : "r"(a[0]), "r"(a[1]), "r"(a[2]), "r"(a[3]), "r"(b[0]), "r"(b[1]));
}

// ---------------- prep: weight conversion only ----------------------------------
__global__ void k_prep(const float* __restrict__ W1, const float* __restrict__ W2) {
    int i = blockIdx.x * blockDim.x + threadIdx.x;
    if (i < FIN * F1) g_W1h[i] = __float2half(W1[i]);
    if (i < FIN * W2C) {
        int k = i / W2C, c = i - k * W2C;
        g_W2h[i] = __float2half(c < CLS ? W2[k * CLS + c] : 0.f);
    }
}

// ---------------- CSR build (independent of prep) -------------------------------
// 4 edges per thread; is64 detected per block
__global__ void k_count(const void* ei) {
    __shared__ int s64;
    if (threadIdx.x == 0) s64 = detect64(ei);
    __syncthreads();
    int is64 = s64;
    int e0 = (blockIdx.x * blockDim.x + threadIdx.x) * 4;
    if (e0 >= ETOT) return;
    int d[4];
    if (e0 + 3 < EE) {
        if (is64) {
            const longlong2* p = (const longlong2*)((const long long*)ei + EE + e0);
            longlong2 v0 = p[0], v1 = p[1];
            d[0] = (int)v0.x; d[1] = (int)v0.y; d[2] = (int)v1.x; d[3] = (int)v1.y;
        } else {
            int4 v = *(const int4*)((const int*)ei + EE + e0);
            d[0] = v.x; d[1] = v.y; d[2] = v.z; d[3] = v.w;
        }
    } else {
        #pragma unroll
        for (int j = 0; j < 4; j++) {
            int e = e0 + j, s;
            if (e < ETOT) decode_edge(ei, is64, e, s, d[j]); else d[j] = -1;
        }
    }
    #pragma unroll
    for (int j = 0; j < 4; j++)
        if (d[j] >= 0) atomicAdd(&g_deg[d[j]], 1);
}

// single-block scan: thread-chunk serial sums + 2-level warp shuffle scan.
// Also re-zeroes g_deg after consuming it (keeps the cross-call invariant
// deg==0 at entry, so no memset node is needed).
__global__ void __launch_bounds__(1024) k_scan() {
    const int CHUNK = (NN + 1023) / 1024;   // 49
    int tid = threadIdx.x;
    int beg = tid * CHUNK, end = min(beg + CHUNK, NN);

    int sum = 0;
    #pragma unroll 7
    for (int i = beg; i < end; i++) sum += __ldg(&g_deg[i]);

    int lane = tid & 31, wid = tid >> 5;
    int v = sum;
    #pragma unroll
    for (int o = 1; o < 32; o <<= 1) {
        int t = __shfl_up_sync(0xffffffffu, v, o);
        if (lane >= o) v += t;
    }
    __shared__ int wsum[32];
    if (lane == 31) wsum[wid] = v;
    __syncthreads();
    if (wid == 0) {
        int w = wsum[lane];
        #pragma unroll
        for (int o = 1; o < 32; o <<= 1) {
            int t = __shfl_up_sync(0xffffffffu, w, o);
            if (lane >= o) w += t;
        }
        wsum[lane] = w;
    }
    __syncthreads();

    int run = v - sum + (wid ? wsum[wid - 1] : 0);   // exclusive prefix
    for (int i = beg; i < end; i++) {
        int d = g_deg[i];
        g_rowptr[i] = run;
        g_cursor[i] = run;
        g_deg[i] = 0;                                // re-arm for next call
        run += d;
    }
    if (tid == 1023) g_rowptr[NN] = run;             // == ETOT
}

// 4 edges per thread
__global__ void k_scatter(const void* ei) {
    __shared__ int s64;
    if (threadIdx.x == 0) s64 = detect64(ei);
    __syncthreads();
    int is64 = s64;
    int e0 = (blockIdx.x * blockDim.x + threadIdx.x) * 4;
    if (e0 >= ETOT) return;
    int s[4], d[4];
    if (e0 + 3 < EE) {
        if (is64) {
            const longlong2* ps = (const longlong2*)((const long long*)ei + e0);
            const longlong2* pd = (const longlong2*)((const long long*)ei + EE + e0);
            longlong2 s0 = ps[0], s1 = ps[1], d0 = pd[0], d1 = pd[1];
            s[0] = (int)s0.x; s[1] = (int)s0.y; s[2] = (int)s1.x; s[3] = (int)s1.y;
            d[0] = (int)d0.x; d[1] = (int)d0.y; d[2] = (int)d1.x; d[3] = (int)d1.y;
        } else {
            int4 vs = *(const int4*)((const int*)ei + e0);
            int4 vd = *(const int4*)((const int*)ei + EE + e0);
            s[0] = vs.x; s[1] = vs.y; s[2] = vs.z; s[3] = vs.w;
            d[0] = vd.x; d[1] = vd.y; d[2] = vd.z; d[3] = vd.w;
        }
    } else {
        #pragma unroll
        for (int j = 0; j < 4; j++) {
            int e = e0 + j;
            if (e < ETOT) decode_edge(ei, is64, e, s[j], d[j]); else d[j] = -1;
        }
    }
    #pragma unroll
    for (int j = 0; j < 4; j++) {
        if (d[j] >= 0) {
            int pos = atomicAdd(&g_cursor[d[j]], 1);
            g_csrc[pos] = s[j];
        }
    }
}

// ---------------- GEMM1 (tensor cores): h1 = x @ W1 + fused attention dots ------
// block = 128 rows; 8 warps as 4(M)x2(N); fp16 mma.m16n8k16, f32 accumulate.
__global__ void __launch_bounds__(256) k_gemm1(
    const float* __restrict__ x,
    const float* __restrict__ asrc, const float* __restrict__ adst)
{
    __shared__ __half sA[128][72];    // x chunk (128 rows x 64 k)
    __shared__ __half sB[64][136];    // W chunk (64 k x 128 cols)

    int tid = threadIdx.x;
    int warp = tid >> 5, lane = tid & 31;
    int wm = warp >> 1, wn = warp & 1;
    int m0 = wm * 32, n0 = wn * 64;
    int rowBase = blockIdx.x * 128;

    float c[2][8][4] = {};

    #pragma unroll
    for (int kc = 0; kc < 2; kc++) {
        __syncthreads();
        // stage A: 128 rows x 64 k (f32 -> fp16), 2 threads per row
        {
            int r = tid >> 1;
            int hb = (tid & 1) * 32;
            int grow = rowBase + r;
            uint4* dst = (uint4*)&sA[r][hb];
            if (grow < NN) {
                const float4* src =
                    (const float4*)(x + (size_t)grow * FIN + kc * 64 + hb);
                #pragma unroll
                for (int i = 0; i < 4; i++) {
                    float4 f0 = src[2 * i], f1 = src[2 * i + 1];
                    uint4 u;
                    u.x = pack2(f0.x, f0.y); u.y = pack2(f0.z, f0.w);
                    u.z = pack2(f1.x, f1.y); u.w = pack2(f1.z, f1.w);
                    dst[i] = u;
                }
            } else {
                #pragma unroll
                for (int i = 0; i < 4; i++) dst[i] = make_uint4(0, 0, 0, 0);
            }
        }
        // stage B: 64 k x 128 cols fp16 copy, 4 threads per k-row
        {
            int k = tid >> 2;
            int q = (tid & 3) * 32;
            const uint4* src = (const uint4*)(g_W1h + (size_t)(kc * 64 + k) * F1 + q);
            uint4* dst = (uint4*)&sB[k][q];
            #pragma unroll
            for (int i = 0; i < 4; i++) dst[i] = src[i];
        }
        __syncthreads();

        #pragma unroll
        for (int kt = 0; kt < 4; kt++) {
            int ks = kt * 16;
            uint32_t a[2][4];
            #pragma unroll
            for (int mi = 0; mi < 2; mi++) {
                int row = m0 + mi * 16 + (lane & 15);
                int col = ks + ((lane >> 4) << 3);
                ldsm4(a[mi], &sA[row][col]);
            }
            uint32_t b[8][2];
            #pragma unroll
            for (int nb = 0; nb < 4; nb++) {
                int krow = ks + (lane & 7) + (((lane >> 3) & 1) << 3);
                int col = n0 + nb * 16 + ((lane >> 4) << 3);
                uint32_t t[4];
                ldsm4t(t, &sB[krow][col]);
                b[2 * nb][0] = t[0]; b[2 * nb][1] = t[1];
                b[2 * nb + 1][0] = t[2]; b[2 * nb + 1][1] = t[3];
            }
            #pragma unroll
            for (int mi = 0; mi < 2; mi++)
                #pragma unroll
                for (int ni = 0; ni < 8; ni++)
                    mma16816(c[mi][ni], a[mi], b[ni]);
        }
    }

    // epilogue: store h1 (fp16) + attention dots (f32 accumulators)
    int q = lane & 3;
    float asv[8][2], adv[8][2];
    #pragma unroll
    for (int ni = 0; ni < 8; ni++) {
        int col = n0 + ni * 8 + q * 2;
        asv[ni][0] = __ldg(&asrc[col]); asv[ni][1] = __ldg(&asrc[col + 1]);
        adv[ni][0] = __ldg(&adst[col]); adv[ni][1] = __ldg(&adst[col + 1]);
    }
    #pragma unroll
    for (int mi = 0; mi < 2; mi++) {
        int rlo = rowBase + m0 + mi * 16 + (lane >> 2);
        int rhi = rlo + 8;
        float ps[2][2] = {}, pd[2][2] = {};
        #pragma unroll
        for (int ni = 0; ni < 8; ni++) {
            float* cc = c[mi][ni];
            int h = ni >> 2;
            ps[h][0] += cc[0] * asv[ni][0] + cc[1] * asv[ni][1];
            pd[h][0] += cc[0] * adv[ni][0] + cc[1] * adv[ni][1];
            ps[h][1] += cc[2] * asv[ni][0] + cc[3] * asv[ni][1];
            pd[h][1] += cc[2] * adv[ni][0] + cc[3] * adv[ni][1];
            int colh = (n0 + ni * 8 + q * 2) >> 1;
            if (rlo < NN)
                g_h1h[(size_t)rlo * 64 + colh] = __floats2half2_rn(cc[0], cc[1]);
            if (rhi < NN)
                g_h1h[(size_t)rhi * 64 + colh] = __floats2half2_rn(cc[2], cc[3]);
        }
        #pragma unroll
        for (int h = 0; h < 2; h++)
            #pragma unroll
            for (int j = 0; j < 2; j++) {
                ps[h][j] += __shfl_xor_sync(0xffffffffu, ps[h][j], 1);
                ps[h][j] += __shfl_xor_sync(0xffffffffu, ps[h][j], 2);
                pd[h][j] += __shfl_xor_sync(0xffffffffu, pd[h][j], 1);
                pd[h][j] += __shfl_xor_sync(0xffffffffu, pd[h][j], 2);
            }
        if (q == 0) {
            if (rlo < NN) {
                g_as1[rlo * HH + wn * 2]     = ps[0][0];
                g_as1[rlo * HH + wn * 2 + 1] = ps[1][0];
                g_ad1[rlo * HH + wn * 2]     = pd[0][0];
                g_ad1[rlo * HH + wn * 2 + 1] = pd[1][0];
            }
            if (rhi < NN) {
                g_as1[rhi * HH + wn * 2]     = ps[0][1];
                g_as1[rhi * HH + wn * 2 + 1] = ps[1][1];
                g_ad1[rhi * HH + wn * 2]     = pd[0][1];
                g_ad1[rhi * HH + wn * 2 + 1] = pd[1][1];
            }
        }
    }
}

// ---------------- fused softmax + aggregation, layer 1 (warp per dst) -----------
__global__ void __launch_bounds__(256) k_fused1() {
    __shared__ float4 s_ex[8][32];
    __shared__ int    s_src[8][32];
    int warp = threadIdx.x >> 5, lane = threadIdx.x & 31;
    int dst = blockIdx.x * 8 + warp;
    if (dst >= NN) return;

    int beg = g_rowptr[dst], end = g_rowptr[dst + 1];
    float4 ad = __ldg((const float4*)g_ad1 + dst);

    int head = lane >> 3;
    float4 den = make_float4(0.f, 0.f, 0.f, 0.f);
    float4 accv = make_float4(0.f, 0.f, 0.f, 0.f);

    for (int base = beg; base < end; base += 32) {
        int i = base + lane;
        float4 ex = make_float4(0.f, 0.f, 0.f, 0.f);
        int s = 0;
        if (i < end) {
            s = __ldg(&g_csrc[i]);
            float4 as = __ldg((const float4*)g_as1 + s);
            ex.x = __expf(lrelu(as.x + ad.x));
            ex.y = __expf(lrelu(as.y + ad.y));
            ex.z = __expf(lrelu(as.z + ad.z));
            ex.w = __expf(lrelu(as.w + ad.w));
            den.x += ex.x; den.y += ex.y; den.z += ex.z; den.w += ex.w;
        }
        s_src[warp][lane] = s;
        s_ex[warp][lane] = ex;
        __syncwarp();
        int cnt = min(32, end - base);
        #pragma unroll 12
        for (int j = 0; j < cnt; j++) {
            int sj = s_src[warp][j];
            float exh = ((const float*)&s_ex[warp][j])[head];
            uint2 hv = *(const uint2*)(g_h1h + (size_t)sj * 64 + lane * 2);
            float2 f0 = __half22float2(u2h(hv.x));
            float2 f1 = __half22float2(u2h(hv.y));
            accv.x += exh * f0.x; accv.y += exh * f0.y;
            accv.z += exh * f1.x; accv.w += exh * f1.y;
        }
        __syncwarp();
    }

    #pragma unroll
    for (int o = 16; o; o >>= 1) {
        den.x += __shfl_xor_sync(0xffffffffu, den.x, o);
        den.y += __shfl_xor_sync(0xffffffffu, den.y, o);
        den.z += __shfl_xor_sync(0xffffffffu, den.z, o);
        den.w += __shfl_xor_sync(0xffffffffu, den.w, o);
    }
    float dh = ((const float*)&den)[head];
    float inv = __fdividef(1.f, dh);
    accv.x *= inv; accv.y *= inv; accv.z *= inv; accv.w *= inv;
    *(float4*)(g_out1 + (size_t)dst * F1 + lane * 4) = accv;
}

// ---------------- GEMM2 (tensor cores): h2 = relu(out1+b1) @ W2 + att dots ------
// block = 128 rows; 8 warps x 16 rows; N=40 (5 n8 tiles), K=128.
__global__ void __launch_bounds__(256) k_gemm2(
    const float* __restrict__ b1,
    const float* __restrict__ asrc, const float* __restrict__ adst)
{
    __shared__ __half sX[128][136];   // 34.8 KB
    __shared__ __half sW[128][72];    // 18.4 KB (cols 0..47 used)

    int tid = threadIdx.x;
    int warp = tid >> 5, lane = tid & 31;
    int rowBase = blockIdx.x * 128;

    // stage X: relu(out1 + b1) -> fp16, 2 threads per row (64 f32 each)
    {
        int r = tid >> 1;
        int hb = (tid & 1) * 64;
        int grow = rowBase + r;
        uint4* dst = (uint4*)&sX[r][hb];
        if (grow < NN) {
            const float4* src = (const float4*)(g_out1 + (size_t)grow * F1 + hb);
            const float4* bsrc = (const float4*)(b1 + hb);
            #pragma unroll
            for (int i = 0; i < 8; i++) {
                float4 f0 = src[2 * i], f1 = src[2 * i + 1];
                float4 b0 = __ldg(&bsrc[2 * i]), b2v = __ldg(&bsrc[2 * i + 1]);
                f0.x = fmaxf(f0.x + b0.x, 0.f);  f0.y = fmaxf(f0.y + b0.y, 0.f);
                f0.z = fmaxf(f0.z + b0.z, 0.f);  f0.w = fmaxf(f0.w + b0.w, 0.f);
                f1.x = fmaxf(f1.x + b2v.x, 0.f); f1.y = fmaxf(f1.y + b2v.y, 0.f);
                f1.z = fmaxf(f1.z + b2v.z, 0.f); f1.w = fmaxf(f1.w + b2v.w, 0.f);
                uint4 u;
                u.x = pack2(f0.x, f0.y); u.y = pack2(f0.z, f0.w);
                u.z = pack2(f1.x, f1.y); u.w = pack2(f1.z, f1.w);
                dst[i] = u;
            }
        } else {
            #pragma unroll
            for (int i = 0; i < 8; i++) dst[i] = make_uint4(0, 0, 0, 0);
        }
    }
    // stage W: 128 k x 48 cols, 2 threads per k-row (24 halves each)
    {
        int k = tid >> 1;
        int off = (tid & 1) * 24;
        const uint4* src = (const uint4*)(g_W2h + k * W2C + off);
        uint4* dst = (uint4*)&sW[k][off];
        dst[0] = src[0]; dst[1] = src[1]; dst[2] = src[2];
    }
    __syncthreads();

    float c[5][4] = {};
    int m0 = warp * 16;

    #pragma unroll
    for (int kt = 0; kt < 8; kt++) {
        int ks = kt * 16;
        uint32_t a[4];
        ldsm4(a, &sX[m0 + (lane & 15)][ks + ((lane >> 4) << 3)]);
        uint32_t b[6][2];
        #pragma unroll
        for (int nb = 0; nb < 3; nb++) {
            int krow = ks + (lane & 7) + (((lane >> 3) & 1) << 3);
            int col = nb * 16 + ((lane >> 4) << 3);
            uint32_t t[4];
            ldsm4t(t, &sW[krow][col]);
            b[2 * nb][0] = t[0]; b[2 * nb][1] = t[1];
            b[2 * nb + 1][0] = t[2]; b[2 * nb + 1][1] = t[3];
        }
        #pragma unroll
        for (int ni = 0; ni < 5; ni++) mma16816(c[ni], a, b[ni]);
    }

    // epilogue
    int q = lane & 3;
    int rlo = rowBase + m0 + (lane >> 2);
    int rhi = rlo + 8;
    float psLo = 0.f, pdLo = 0.f, psHi = 0.f, pdHi = 0.f;
    #pragma unroll
    for (int ni = 0; ni < 5; ni++) {
        int col = ni * 8 + q * 2;
        float a0 = __ldg(&asrc[col]), a1 = __ldg(&asrc[col + 1]);
        float d0 = __ldg(&adst[col]), d1 = __ldg(&adst[col + 1]);
        float* cc = c[ni];
        psLo += cc[0] * a0 + cc[1] * a1;  pdLo += cc[0] * d0 + cc[1] * d1;
        psHi += cc[2] * a0 + cc[3] * a1;  pdHi += cc[2] * d0 + cc[3] * d1;
        if (rlo < NN)
            *(__half2*)(g_h2h + (size_t)rlo * CLS + col) =
                __floats2half2_rn(cc[0], cc[1]);
        if (rhi < NN)
            *(__half2*)(g_h2h + (size_t)rhi * CLS + col) =
                __floats2half2_rn(cc[2], cc[3]);
    }
    psLo += __shfl_xor_sync(0xffffffffu, psLo, 1);
    psLo += __shfl_xor_sync(0xffffffffu, psLo, 2);
    pdLo += __shfl_xor_sync(0xffffffffu, pdLo, 1);
    pdLo += __shfl_xor_sync(0xffffffffu, pdLo, 2);
    psHi += __shfl_xor_sync(0xffffffffu, psHi, 1);
    psHi += __shfl_xor_sync(0xffffffffu, psHi, 2);
    pdHi += __shfl_xor_sync(0xffffffffu, pdHi, 1);
    pdHi += __shfl_xor_sync(0xffffffffu, pdHi, 2);
    if (q == 0) {
        if (rlo < NN) { g_as2[rlo] = psLo; g_ad2[rlo] = pdLo; }
        if (rhi < NN) { g_as2[rhi] = psHi; g_ad2[rhi] = pdHi; }
    }
}

// ---------------- fused softmax + aggregation, layer 2 (warp per dst) -----------
__global__ void __launch_bounds__(256) k_fused2(
    float* __restrict__ out, const float* __restrict__ b2)
{
    __shared__ float s_exs[8][32];
    __shared__ int   s_src[8][32];
    int warp = threadIdx.x >> 5, lane = threadIdx.x & 31;
    int dst = blockIdx.x * 8 + warp;
    if (dst >= NN) return;

    int beg = g_rowptr[dst], end = g_rowptr[dst + 1];
    float adv = __ldg(&g_ad2[dst]);

    float den = 0.f, acc0 = 0.f, acc1 = 0.f;
    bool two = lane < 8;

    for (int base = beg; base < end; base += 32) {
        int i = base + lane;
        float ex = 0.f;
        int s = 0;
        if (i < end) {
            s = __ldg(&g_csrc[i]);
            ex = __expf(lrelu(__ldg(&g_as2[s]) + adv));
            den += ex;
        }
        s_src[warp][lane] = s;
        s_exs[warp][lane] = ex;
        __syncwarp();
        int cnt = min(32, end - base);
        #pragma unroll 16
        for (int j = 0; j < cnt; j++) {
            int sj = s_src[warp][j];
            float exj = s_exs[warp][j];
            acc0 += exj * __half2float(g_h2h[(size_t)sj * CLS + lane]);
            if (two) acc1 += exj * __half2float(g_h2h[(size_t)sj * CLS + 32 + lane]);
        }
        __syncwarp();
    }

    #pragma unroll
    for (int o = 16; o; o >>= 1)
        den += __shfl_xor_sync(0xffffffffu, den, o);
    float inv = __fdividef(1.f, den);

    out[(size_t)dst * CLS + lane] = acc0 * inv + __ldg(&b2[lane]);
    if (two)
        out[(size_t)dst * CLS + 32 + lane] = acc1 * inv + __ldg(&b2[32 + lane]);
}

// ---------------- launch --------------------------------------------------------
extern "C" void kernel_launch(void* const* d_in, const int* in_sizes, int n_in,
                              void* d_out, int out_size) {
    const float* x   = (const float*)d_in[0];
    const void*  ei  = d_in[1];
    const float* W1  = (const float*)d_in[2];
    const float* as1 = (const float*)d_in[3];
    const float* ad1 = (const float*)d_in[4];
    const float* b1  = (const float*)d_in[5];
    const float* W2  = (const float*)d_in[6];
    const float* as2 = (const float*)d_in[7];
    const float* ad2 = (const float*)d_in[8];
    const float* b2  = (const float*)d_in[9];
    float* out = (float*)d_out;

    static cudaStream_t s2 = nullptr;
    static cudaEvent_t ev_fork, ev_csr;
    if (!s2) {
        cudaStreamCreateWithFlags(&s2, cudaStreamNonBlocking);
        cudaEventCreateWithFlags(&ev_fork, cudaEventDisableTiming);
        cudaEventCreateWithFlags(&ev_csr, cudaEventDisableTiming);
    }

    const int EB = (ETOT / 4 + 255) / 256;   // 4 edges per thread

    // fork side stream; CSR build starts at t=0, independent of prep.
    // g_deg is 0 at entry (BSS on first call; re-zeroed by k_scan each call).
    cudaEventRecord(ev_fork, 0);
    cudaStreamWaitEvent(s2, ev_fork, 0);

    // main stream: weight conversion, then gemm1 (concurrent with CSR build)
    k_prep<<<(FIN * F1 + 255) / 256, 256>>>(W1, W2);
    k_count<<<EB, 256, 0, s2>>>(ei);
    k_scan<<<1, 1024, 0, s2>>>();
    k_scatter<<<EB, 256, 0, s2>>>(ei);
    cudaEventRecord(ev_csr, s2);

    k_gemm1<<<(NN + 127) / 128, 256>>>(x, as1, ad1);

    cudaStreamWaitEvent(0, ev_csr, 0);
    k_fused1<<<(NN + 7) / 8, 256>>>();
    k_gemm2<<<(NN + 127) / 128, 256>>>(b1, as2, ad2);
    k_fused2<<<(NN + 7) / 8, 256>>>(out, b2);
}

// round 17
// speedup vs baseline: 1.8849x; 1.8849x over previous
#include <cuda_runtime.h>
#include <cuda_fp16.h>
#include <cstdint>

#define NN   50000
#define EE   800000
#define ETOT 850000            // EE + NN self loops
#define FIN  128
#define HH   4
#define HID  32
#define F1   128               // HH*HID
#define CLS  40
#define W2C  48                // padded W2 cols
#define NEG  0.2f

// ---------------- scratch -----------------------------------------------------
__device__ __half2 g_h1h[(size_t)NN * 64];   // h1 in fp16, 64 half2 per row
__device__ __half  g_W1h[FIN * F1];          // W1 in fp16, [k][c]
__device__ __half  g_W2h[FIN * W2C];         // W2 in fp16, [k][c], cols 40..47 = 0
__device__ __half2 g_b1h[64];                // b1 in fp16 pairs
__device__ float  g_as1[NN * HH];
__device__ float  g_ad1[NN * HH];
__device__ __half2 g_o1h[(size_t)NN * 64];   // layer-1 output in fp16 pairs
__device__ __half g_h2h[(size_t)NN * CLS];   // h2 in fp16
__device__ float  g_as2[NN];
__device__ float  g_ad2[NN];
__device__ int    g_deg[NN];
__device__ int    g_rowptr[NN + 1];
__device__ int    g_cursor[NN];
__device__ int    g_csrc[ETOT];              // src ids sorted by dst
__device__ int    g_is64;

// ---------------- helpers ------------------------------------------------------
__device__ __forceinline__ float lrelu(float v) { return v > 0.f ? v : NEG * v; }

__device__ __forceinline__ __half2 u2h(unsigned u) {
    return *reinterpret_cast<__half2*>(&u);
}
__device__ __forceinline__ unsigned h2u(__half2 h) {
    return *reinterpret_cast<unsigned*>(&h);
}
__device__ __forceinline__ unsigned pack2(float a, float b) {
    __half2 h = __floats2half2_rn(a, b);
    return *reinterpret_cast<unsigned*>(&h);
}

__device__ __forceinline__ void decode_edge(const void* ei, int e, int& s, int& d) {
    if (e < EE) {
        if (g_is64) {
            const long long* p = (const long long*)ei;
            s = (int)p[e];
            d = (int)p[EE + e];
        } else {
            const int* p = (const int*)ei;
            s = p[e];
            d = p[EE + e];
        }
    } else {
        s = d = e - EE;  // self loop
    }
}

__device__ __forceinline__ void ldsm4(uint32_t* r, const void* p) {
    unsigned a = (unsigned)__cvta_generic_to_shared(p);
    asm volatile("ldmatrix.sync.aligned.m8n8.x4.shared.b16 {%0,%1,%2,%3}, [%4];"
        : "=r"(r[0]), "=r"(r[1]), "=r"(r[2]), "=r"(r[3]) : "r"(a));
}
__device__ __forceinline__ void ldsm4t(uint32_t* r, const void* p) {
    unsigned a = (unsigned)__cvta_generic_to_shared(p);
    asm volatile("ldmatrix.sync.aligned.m8n8.x4.trans.shared.b16 {%0,%1,%2,%3}, [%4];"
        : "=r"(r[0]), "=r"(r[1]), "=r"(r[2]), "=r"(r[3]) : "r"(a));
}
__device__ __forceinline__ void mma16816(float* c, const uint32_t* a,
                                         const uint32_t* b) {
    asm volatile("mma.sync.aligned.m16n8k16.row.col.f32.f16.f16.f32 "
        "{%0,%1,%2,%3}, {%4,%5,%6,%7}, {%8,%9}, {%0,%1,%2,%3};"
        : "+f"(c[0]), "+f"(c[1]), "+f"(c[2]), "+f"(c[3])
        : "r"(a[0]), "r"(a[1]), "r"(a[2]), "r"(a[3]), "r"(b[0]), "r"(b[1]));
}

// ---------------- setup kernels -------------------------------------------------
// Grid MUST cover NN (deg zeroing) — launched with (NN+255)/256 blocks.
__global__ void k_prep(const float* __restrict__ W1, const float* __restrict__ W2,
                       const float* __restrict__ b1, const void* ei) {
    int i = blockIdx.x * blockDim.x + threadIdx.x;
    if (i == 0) {
        const int* p = (const int*)ei;
        int is64 = 1;
        for (int j = 0; j < 32; j++)
            if (p[2 * j + 1] != 0) is64 = 0;
        g_is64 = is64;
    }
    if (i < NN) g_deg[i] = 0;
    if (i < FIN * F1) g_W1h[i] = __float2half(W1[i]);
    if (i < FIN * W2C) {
        int k = i / W2C, c = i - k * W2C;
        g_W2h[i] = __float2half(c < CLS ? W2[k * CLS + c] : 0.f);
    }
    if (i < 64) g_b1h[i] = __floats2half2_rn(b1[2 * i], b1[2 * i + 1]);
}

// 4 edges per thread for MLP
__global__ void k_count(const void* ei) {
    int e0 = (blockIdx.x * blockDim.x + threadIdx.x) * 4;
    if (e0 >= ETOT) return;
    int d[4];
    if (e0 + 3 < EE) {
        if (g_is64) {
            const longlong2* p = (const longlong2*)((const long long*)ei + EE + e0);
            longlong2 v0 = p[0], v1 = p[1];
            d[0] = (int)v0.x; d[1] = (int)v0.y; d[2] = (int)v1.x; d[3] = (int)v1.y;
        } else {
            int4 v = *(const int4*)((const int*)ei + EE + e0);
            d[0] = v.x; d[1] = v.y; d[2] = v.z; d[3] = v.w;
        }
    } else {
        #pragma unroll
        for (int j = 0; j < 4; j++) {
            int e = e0 + j, s;
            if (e < ETOT) decode_edge(ei, e, s, d[j]); else d[j] = -1;
        }
    }
    #pragma unroll
    for (int j = 0; j < 4; j++)
        if (d[j] >= 0) atomicAdd(&g_deg[d[j]], 1);
}

// single-block scan: thread-chunk serial sums + 2-level warp shuffle scan
__global__ void __launch_bounds__(1024) k_scan() {
    const int CHUNK = (NN + 1023) / 1024;   // 49
    int tid = threadIdx.x;
    int beg = tid * CHUNK, end = min(beg + CHUNK, NN);

    int sum = 0;
    #pragma unroll 7
    for (int i = beg; i < end; i++) sum += __ldg(&g_deg[i]);

    int lane = tid & 31, wid = tid >> 5;
    int v = sum;
    #pragma unroll
    for (int o = 1; o < 32; o <<= 1) {
        int t = __shfl_up_sync(0xffffffffu, v, o);
        if (lane >= o) v += t;
    }
    __shared__ int wsum[32];
    if (lane == 31) wsum[wid] = v;
    __syncthreads();
    if (wid == 0) {
        int w = wsum[lane];
        #pragma unroll
        for (int o = 1; o < 32; o <<= 1) {
            int t = __shfl_up_sync(0xffffffffu, w, o);
            if (lane >= o) w += t;
        }
        wsum[lane] = w;
    }
    __syncthreads();

    int run = v - sum + (wid ? wsum[wid - 1] : 0);   // exclusive prefix
    for (int i = beg; i < end; i++) {
        int d = g_deg[i];
        g_rowptr[i] = run;
        g_cursor[i] = run;
        run += d;
    }
    if (tid == 1023) g_rowptr[NN] = run;             // == ETOT
}

// 4 edges per thread
__global__ void k_scatter(const void* ei) {
    int e0 = (blockIdx.x * blockDim.x + threadIdx.x) * 4;
    if (e0 >= ETOT) return;
    int s[4], d[4];
    if (e0 + 3 < EE) {
        if (g_is64) {
            const longlong2* ps = (const longlong2*)((const long long*)ei + e0);
            const longlong2* pd = (const longlong2*)((const long long*)ei + EE + e0);
            longlong2 s0 = ps[0], s1 = ps[1], d0 = pd[0], d1 = pd[1];
            s[0] = (int)s0.x; s[1] = (int)s0.y; s[2] = (int)s1.x; s[3] = (int)s1.y;
            d[0] = (int)d0.x; d[1] = (int)d0.y; d[2] = (int)d1.x; d[3] = (int)d1.y;
        } else {
            int4 vs = *(const int4*)((const int*)ei + e0);
            int4 vd = *(const int4*)((const int*)ei + EE + e0);
            s[0] = vs.x; s[1] = vs.y; s[2] = vs.z; s[3] = vs.w;
            d[0] = vd.x; d[1] = vd.y; d[2] = vd.z; d[3] = vd.w;
        }
    } else {
        #pragma unroll
        for (int j = 0; j < 4; j++) {
            int e = e0 + j;
            if (e < ETOT) decode_edge(ei, e, s[j], d[j]); else d[j] = -1;
        }
    }
    #pragma unroll
    for (int j = 0; j < 4; j++) {
        if (d[j] >= 0) {
            int pos = atomicAdd(&g_cursor[d[j]], 1);
            g_csrc[pos] = s[j];
        }
    }
}

// ---------------- GEMM1 (tensor cores): h1 = x @ W1 + fused attention dots ------
// block = 128 rows; 8 warps as 4(M)x2(N); fp16 mma.m16n8k16, f32 accumulate.
__global__ void __launch_bounds__(256) k_gemm1(
    const float* __restrict__ x,
    const float* __restrict__ asrc, const float* __restrict__ adst)
{
    __shared__ __half sA[128][72];    // x chunk (128 rows x 64 k)
    __shared__ __half sB[64][136];    // W chunk (64 k x 128 cols)

    int tid = threadIdx.x;
    int warp = tid >> 5, lane = tid & 31;
    int wm = warp >> 1, wn = warp & 1;
    int m0 = wm * 32, n0 = wn * 64;
    int rowBase = blockIdx.x * 128;

    float c[2][8][4] = {};

    #pragma unroll
    for (int kc = 0; kc < 2; kc++) {
        __syncthreads();
        // stage A: 128 rows x 64 k (f32 -> fp16), 2 threads per row
        {
            int r = tid >> 1;
            int hb = (tid & 1) * 32;
            int grow = rowBase + r;
            uint4* dst = (uint4*)&sA[r][hb];
            if (grow < NN) {
                const float4* src =
                    (const float4*)(x + (size_t)grow * FIN + kc * 64 + hb);
                #pragma unroll
                for (int i = 0; i < 4; i++) {
                    float4 f0 = src[2 * i], f1 = src[2 * i + 1];
                    uint4 u;
                    u.x = pack2(f0.x, f0.y); u.y = pack2(f0.z, f0.w);
                    u.z = pack2(f1.x, f1.y); u.w = pack2(f1.z, f1.w);
                    dst[i] = u;
                }
            } else {
                #pragma unroll
                for (int i = 0; i < 4; i++) dst[i] = make_uint4(0, 0, 0, 0);
            }
        }
        // stage B: 64 k x 128 cols fp16 copy, 4 threads per k-row
        {
            int k = tid >> 2;
            int q = (tid & 3) * 32;
            const uint4* src = (const uint4*)(g_W1h + (size_t)(kc * 64 + k) * F1 + q);
            uint4* dst = (uint4*)&sB[k][q];
            #pragma unroll
            for (int i = 0; i < 4; i++) dst[i] = src[i];
        }
        __syncthreads();

        #pragma unroll
        for (int kt = 0; kt < 4; kt++) {
            int ks = kt * 16;
            uint32_t a[2][4];
            #pragma unroll
            for (int mi = 0; mi < 2; mi++) {
                int row = m0 + mi * 16 + (lane & 15);
                int col = ks + ((lane >> 4) << 3);
                ldsm4(a[mi], &sA[row][col]);
            }
            uint32_t b[8][2];
            #pragma unroll
            for (int nb = 0; nb < 4; nb++) {
                int krow = ks + (lane & 7) + (((lane >> 3) & 1) << 3);
                int col = n0 + nb * 16 + ((lane >> 4) << 3);
                uint32_t t[4];
                ldsm4t(t, &sB[krow][col]);
                b[2 * nb][0] = t[0]; b[2 * nb][1] = t[1];
                b[2 * nb + 1][0] = t[2]; b[2 * nb + 1][1] = t[3];
            }
            #pragma unroll
            for (int mi = 0; mi < 2; mi++)
                #pragma unroll
                for (int ni = 0; ni < 8; ni++)
                    mma16816(c[mi][ni], a[mi], b[ni]);
        }
    }

    // epilogue: store h1 (fp16) + attention dots (f32 accumulators)
    int q = lane & 3;
    float asv[8][2], adv[8][2];
    #pragma unroll
    for (int ni = 0; ni < 8; ni++) {
        int col = n0 + ni * 8 + q * 2;
        asv[ni][0] = __ldg(&asrc[col]); asv[ni][1] = __ldg(&asrc[col + 1]);
        adv[ni][0] = __ldg(&adst[col]); adv[ni][1] = __ldg(&adst[col + 1]);
    }
    #pragma unroll
    for (int mi = 0; mi < 2; mi++) {
        int rlo = rowBase + m0 + mi * 16 + (lane >> 2);
        int rhi = rlo + 8;
        float ps[2][2] = {}, pd[2][2] = {};
        #pragma unroll
        for (int ni = 0; ni < 8; ni++) {
            float* cc = c[mi][ni];
            int h = ni >> 2;
            ps[h][0] += cc[0] * asv[ni][0] + cc[1] * asv[ni][1];
            pd[h][0] += cc[0] * adv[ni][0] + cc[1] * adv[ni][1];
            ps[h][1] += cc[2] * asv[ni][0] + cc[3] * asv[ni][1];
            pd[h][1] += cc[2] * adv[ni][0] + cc[3] * adv[ni][1];
            int colh = (n0 + ni * 8 + q * 2) >> 1;
            if (rlo < NN)
                g_h1h[(size_t)rlo * 64 + colh] = __floats2half2_rn(cc[0], cc[1]);
            if (rhi < NN)
                g_h1h[(size_t)rhi * 64 + colh] = __floats2half2_rn(cc[2], cc[3]);
        }
        #pragma unroll
        for (int h = 0; h < 2; h++)
            #pragma unroll
            for (int j = 0; j < 2; j++) {
                ps[h][j] += __shfl_xor_sync(0xffffffffu, ps[h][j], 1);
                ps[h][j] += __shfl_xor_sync(0xffffffffu, ps[h][j], 2);
                pd[h][j] += __shfl_xor_sync(0xffffffffu, pd[h][j], 1);
                pd[h][j] += __shfl_xor_sync(0xffffffffu, pd[h][j], 2);
            }
        if (q == 0) {
            if (rlo < NN) {
                g_as1[rlo * HH + wn * 2]     = ps[0][0];
                g_as1[rlo * HH + wn * 2 + 1] = ps[1][0];
                g_ad1[rlo * HH + wn * 2]     = pd[0][0];
                g_ad1[rlo * HH + wn * 2 + 1] = pd[1][0];
            }
            if (rhi < NN) {
                g_as1[rhi * HH + wn * 2]     = ps[0][1];
                g_as1[rhi * HH + wn * 2 + 1] = ps[1][1];
                g_ad1[rhi * HH + wn * 2]     = pd[0][1];
                g_ad1[rhi * HH + wn * 2 + 1] = pd[1][1];
            }
        }
    }
}

// ---------------- fused softmax + aggregation, layer 1 (warp per dst) -----------
__global__ void __launch_bounds__(256) k_fused1() {
    __shared__ float4 s_ex[8][32];
    __shared__ int    s_src[8][32];
    int warp = threadIdx.x >> 5, lane = threadIdx.x & 31;
    int dst = blockIdx.x * 8 + warp;
    if (dst >= NN) return;

    int beg = g_rowptr[dst], end = g_rowptr[dst + 1];
    float4 ad = __ldg((const float4*)g_ad1 + dst);

    int head = lane >> 3;
    float4 den = make_float4(0.f, 0.f, 0.f, 0.f);
    float4 accv = make_float4(0.f, 0.f, 0.f, 0.f);

    for (int base = beg; base < end; base += 32) {
        int i = base + lane;
        float4 ex = make_float4(0.f, 0.f, 0.f, 0.f);
        int s = 0;
        if (i < end) {
            s = __ldg(&g_csrc[i]);
            float4 as = __ldg((const float4*)g_as1 + s);
            ex.x = __expf(lrelu(as.x + ad.x));
            ex.y = __expf(lrelu(as.y + ad.y));
            ex.z = __expf(lrelu(as.z + ad.z));
            ex.w = __expf(lrelu(as.w + ad.w));
            den.x += ex.x; den.y += ex.y; den.z += ex.z; den.w += ex.w;
        }
        s_src[warp][lane] = s;
        s_ex[warp][lane] = ex;
        __syncwarp();
        int cnt = min(32, end - base);
        #pragma unroll 8
        for (int j = 0; j < cnt; j++) {
            int sj = s_src[warp][j];
            float exh = ((const float*)&s_ex[warp][j])[head];
            uint2 hv = *(const uint2*)(g_h1h + (size_t)sj * 64 + lane * 2);
            float2 f0 = __half22float2(u2h(hv.x));
            float2 f1 = __half22float2(u2h(hv.y));
            accv.x += exh * f0.x; accv.y += exh * f0.y;
            accv.z += exh * f1.x; accv.w += exh * f1.y;
        }
        __syncwarp();
    }

    #pragma unroll
    for (int o = 16; o; o >>= 1) {
        den.x += __shfl_xor_sync(0xffffffffu, den.x, o);
        den.y += __shfl_xor_sync(0xffffffffu, den.y, o);
        den.z += __shfl_xor_sync(0xffffffffu, den.z, o);
        den.w += __shfl_xor_sync(0xffffffffu, den.w, o);
    }
    float dh = ((const float*)&den)[head];
    float inv = __fdividef(1.f, dh);
    // store layer-1 output in fp16 pairs (2 half2 = cols lane*4 .. lane*4+3)
    __half2 o0 = __floats2half2_rn(accv.x * inv, accv.y * inv);
    __half2 o1 = __floats2half2_rn(accv.z * inv, accv.w * inv);
    *(uint2*)(g_o1h + (size_t)dst * 64 + lane * 2) = make_uint2(h2u(o0), h2u(o1));
}

// ---------------- GEMM2 (tensor cores): h2 = relu(out1+b1) @ W2 + att dots ------
// block = 128 rows; 8 warps x 16 rows; N=40 (5 n8 tiles), K=128.
// X staged from fp16 out1 via half2 relu+bias (copy path, no f32 convert).
__global__ void __launch_bounds__(256) k_gemm2(
    const float* __restrict__ asrc, const float* __restrict__ adst)
{
    __shared__ __half sX[128][136];   // 34.8 KB
    __shared__ __half sW[128][72];    // 18.4 KB (cols 0..47 used)

    int tid = threadIdx.x;
    int warp = tid >> 5, lane = tid & 31;
    int rowBase = blockIdx.x * 128;

    // stage X: relu(o1h + b1h) in half2, 2 threads per row (32 half2 each)
    {
        int r = tid >> 1;
        int hb = (tid & 1) * 32;                 // half2 offset in row
        int grow = rowBase + r;
        uint4* dst = (uint4*)&sX[r][hb * 2];
        if (grow < NN) {
            const uint4* src = (const uint4*)(g_o1h + (size_t)grow * 64 + hb);
            const __half2 z2 = __floats2half2_rn(0.f, 0.f);
            #pragma unroll
            for (int i = 0; i < 8; i++) {        // 8 uint4 = 32 half2
                uint4 u = src[i];
                __half2 b0 = g_b1h[hb + 4 * i + 0];
                __half2 b1v = g_b1h[hb + 4 * i + 1];
                __half2 b2v = g_b1h[hb + 4 * i + 2];
                __half2 b3v = g_b1h[hb + 4 * i + 3];
                u.x = h2u(__hmax2(__hadd2(u2h(u.x), b0), z2));
                u.y = h2u(__hmax2(__hadd2(u2h(u.y), b1v), z2));
                u.z = h2u(__hmax2(__hadd2(u2h(u.z), b2v), z2));
                u.w = h2u(__hmax2(__hadd2(u2h(u.w), b3v), z2));
                dst[i] = u;
            }
        } else {
            #pragma unroll
            for (int i = 0; i < 8; i++) dst[i] = make_uint4(0, 0, 0, 0);
        }
    }
    // stage W: 128 k x 48 cols, 2 threads per k-row (24 halves each)
    {
        int k = tid >> 1;
        int off = (tid & 1) * 24;
        const uint4* src = (const uint4*)(g_W2h + k * W2C + off);
        uint4* dst = (uint4*)&sW[k][off];
        dst[0] = src[0]; dst[1] = src[1]; dst[2] = src[2];
    }
    __syncthreads();

    float c[5][4] = {};
    int m0 = warp * 16;

    #pragma unroll
    for (int kt = 0; kt < 8; kt++) {
        int ks = kt * 16;
        uint32_t a[4];
        ldsm4(a, &sX[m0 + (lane & 15)][ks + ((lane >> 4) << 3)]);
        uint32_t b[6][2];
        #pragma unroll
        for (int nb = 0; nb < 3; nb++) {
            int krow = ks + (lane & 7) + (((lane >> 3) & 1) << 3);
            int col = nb * 16 + ((lane >> 4) << 3);
            uint32_t t[4];
            ldsm4t(t, &sW[krow][col]);
            b[2 * nb][0] = t[0]; b[2 * nb][1] = t[1];
            b[2 * nb + 1][0] = t[2]; b[2 * nb + 1][1] = t[3];
        }
        #pragma unroll
        for (int ni = 0; ni < 5; ni++) mma16816(c[ni], a, b[ni]);
    }

    // epilogue
    int q = lane & 3;
    int rlo = rowBase + m0 + (lane >> 2);
    int rhi = rlo + 8;
    float psLo = 0.f, pdLo = 0.f, psHi = 0.f, pdHi = 0.f;
    #pragma unroll
    for (int ni = 0; ni < 5; ni++) {
        int col = ni * 8 + q * 2;
        float a0 = __ldg(&asrc[col]), a1 = __ldg(&asrc[col + 1]);
        float d0 = __ldg(&adst[col]), d1 = __ldg(&adst[col + 1]);
        float* cc = c[ni];
        psLo += cc[0] * a0 + cc[1] * a1;  pdLo += cc[0] * d0 + cc[1] * d1;
        psHi += cc[2] * a0 + cc[3] * a1;  pdHi += cc[2] * d0 + cc[3] * d1;
        if (rlo < NN)
            *(__half2*)(g_h2h + (size_t)rlo * CLS + col) =
                __floats2half2_rn(cc[0], cc[1]);
        if (rhi < NN)
            *(__half2*)(g_h2h + (size_t)rhi * CLS + col) =
                __floats2half2_rn(cc[2], cc[3]);
    }
    psLo += __shfl_xor_sync(0xffffffffu, psLo, 1);
    psLo += __shfl_xor_sync(0xffffffffu, psLo, 2);
    pdLo += __shfl_xor_sync(0xffffffffu, pdLo, 1);
    pdLo += __shfl_xor_sync(0xffffffffu, pdLo, 2);
    psHi += __shfl_xor_sync(0xffffffffu, psHi, 1);
    psHi += __shfl_xor_sync(0xffffffffu, psHi, 2);
    pdHi += __shfl_xor_sync(0xffffffffu, pdHi, 1);
    pdHi += __shfl_xor_sync(0xffffffffu, pdHi, 2);
    if (q == 0) {
        if (rlo < NN) { g_as2[rlo] = psLo; g_ad2[rlo] = pdLo; }
        if (rhi < NN) { g_as2[rhi] = psHi; g_ad2[rhi] = pdHi; }
    }
}

// ---------------- fused softmax + aggregation, layer 2 (warp per dst) -----------
__global__ void __launch_bounds__(256) k_fused2(
    float* __restrict__ out, const float* __restrict__ b2)
{
    __shared__ float s_exs[8][32];
    __shared__ int   s_src[8][32];
    int warp = threadIdx.x >> 5, lane = threadIdx.x & 31;
    int dst = blockIdx.x * 8 + warp;
    if (dst >= NN) return;

    int beg = g_rowptr[dst], end = g_rowptr[dst + 1];
    float adv = __ldg(&g_ad2[dst]);

    float den = 0.f, acc0 = 0.f, acc1 = 0.f;
    bool two = lane < 8;

    for (int base = beg; base < end; base += 32) {
        int i = base + lane;
        float ex = 0.f;
        int s = 0;
        if (i < end) {
            s = __ldg(&g_csrc[i]);
            ex = __expf(lrelu(__ldg(&g_as2[s]) + adv));
            den += ex;
        }
        s_src[warp][lane] = s;
        s_exs[warp][lane] = ex;
        __syncwarp();
        int cnt = min(32, end - base);
        #pragma unroll 8
        for (int j = 0; j < cnt; j++) {
            int sj = s_src[warp][j];
            float exj = s_exs[warp][j];
            acc0 += exj * __half2float(g_h2h[(size_t)sj * CLS + lane]);
            if (two) acc1 += exj * __half2float(g_h2h[(size_t)sj * CLS + 32 + lane]);
        }
        __syncwarp();
    }

    #pragma unroll
    for (int o = 16; o; o >>= 1)
        den += __shfl_xor_sync(0xffffffffu, den, o);
    float inv = __fdividef(1.f, den);

    out[(size_t)dst * CLS + lane] = acc0 * inv + __ldg(&b2[lane]);
    if (two)
        out[(size_t)dst * CLS + 32 + lane] = acc1 * inv + __ldg(&b2[32 + lane]);
}

// ---------------- launch --------------------------------------------------------
extern "C" void kernel_launch(void* const* d_in, const int* in_sizes, int n_in,
                              void* d_out, int out_size) {
    const float* x   = (const float*)d_in[0];
    const void*  ei  = d_in[1];
    const float* W1  = (const float*)d_in[2];
    const float* as1 = (const float*)d_in[3];
    const float* ad1 = (const float*)d_in[4];
    const float* b1  = (const float*)d_in[5];
    const float* W2  = (const float*)d_in[6];
    const float* as2 = (const float*)d_in[7];
    const float* ad2 = (const float*)d_in[8];
    const float* b2  = (const float*)d_in[9];
    float* out = (float*)d_out;

    static cudaStream_t s2 = nullptr;
    static cudaEvent_t ev_prep, ev_csr;
    if (!s2) {
        cudaStreamCreateWithFlags(&s2, cudaStreamNonBlocking);
        cudaEventCreateWithFlags(&ev_prep, cudaEventDisableTiming);
        cudaEventCreateWithFlags(&ev_csr, cudaEventDisableTiming);
    }

    const int EB = (ETOT / 4 + 255) / 256;   // 4 edges per thread

    // main stream: prep (weights, b1, is64, deg=0) — grid covers NN!
    k_prep<<<(NN + 255) / 256, 256>>>(W1, W2, b1, ei);
    cudaEventRecord(ev_prep, 0);

    // side stream: CSR build, overlapped with gemm1
    cudaStreamWaitEvent(s2, ev_prep, 0);
    k_count<<<EB, 256, 0, s2>>>(ei);
    k_scan<<<1, 1024, 0, s2>>>();
    k_scatter<<<EB, 256, 0, s2>>>(ei);
    cudaEventRecord(ev_csr, s2);

    // main stream: dense transform overlapped with CSR build
    k_gemm1<<<(NN + 127) / 128, 256>>>(x, as1, ad1);

    cudaStreamWaitEvent(0, ev_csr, 0);
    k_fused1<<<(NN + 7) / 8, 256>>>();
    k_gemm2<<<(NN + 127) / 128, 256>>>(as2, ad2);
    k_fused2<<<(NN + 7) / 8, 256>>>(out, b2);
}